// round 8
// baseline (speedup 1.0000x reference)
#include <cuda_runtime.h>
#include <cuda_bf16.h>

// Problem constants
#define Bx 4
#define Cx 3
#define Hx 224
#define Wx 224
#define Kx 196
#define Ex 768
#define HW (Hx * Wx)               // 50176
#define KC (Kx * Cx)               // 588
#define BK (Bx * Kx)               // 784

#define BPB 49                     // blocks per batch
#define NBLK (Bx * BPB)            // 196 total blocks
#define TA 1024                    // threads per block: 1 pixel per thread
#define ROWS_PER_BLOCK (BK / NBLK) // 4

#define NREP 4                     // global-pool replicas
#define ROW_F4 8                   // 128 B per (b,k) row

// Replicated pooled sums: g_pool4[rep][bk][ROW_F4]; element 0 = {c0,c1,c2,pad}.
// Zero at module load; phase 2 re-zeroes consumed rows each call.
__device__ float4 g_pool4[NREP * BK * ROW_F4];

// Grid barrier: monotone epoch counter (never reset; u64 cannot overflow).
__device__ unsigned long long g_bar;

__device__ __forceinline__ void red_add_v4(float4* p, float x, float y, float z) {
    asm volatile("red.global.add.v4.f32 [%0], {%1, %2, %3, %4};"
                 :: "l"(p), "f"(x), "f"(y), "f"(z), "f"(0.0f) : "memory");
}

__device__ __forceinline__ float4 ldcg4(const float4* p) {
    float4 v;
    asm volatile("ld.global.cg.v4.f32 {%0,%1,%2,%3}, [%4];"
                 : "=f"(v.x), "=f"(v.y), "=f"(v.z), "=f"(v.w) : "l"(p));
    return v;
}

__global__ void __launch_bounds__(TA, 2)
fused_kernel(const float* __restrict__ img,
             const int* __restrict__ seg,
             const float* __restrict__ Wmat,
             const float* __restrict__ bias,
             float* __restrict__ out) {
    __shared__ float s_pool[KC];

    const int tid = threadIdx.x;
    const int b   = blockIdx.x / BPB;
    const int blk = blockIdx.x % BPB;
    const int rep = blockIdx.x & (NREP - 1);

    // ---------------- Phase 1: segment-sum, 1 pixel per thread ----------------
    if (tid < KC) s_pool[tid] = 0.0f;
    __syncthreads();

    const int p = blk * TA + tid;                 // 49*1024 = HW exactly
    const float* img_b = img + (size_t)b * Cx * HW;
    const int*   seg_b = seg + (size_t)b * HW;

    int   k  = seg_b[p];
    float v0 = img_b[p];
    float v1 = img_b[p + HW];
    float v2 = img_b[p + 2 * HW];

    atomicAdd(&s_pool[k * Cx + 0], v0);
    atomicAdd(&s_pool[k * Cx + 1], v1);
    atomicAdd(&s_pool[k * Cx + 2], v2);

    __syncthreads();

    // Flush block partials into this block's replica (one v4 RED per key)
    float4* pool_rb = g_pool4 + ((size_t)rep * BK + (size_t)b * Kx) * ROW_F4;
    if (tid < Kx) {
        float c0 = s_pool[tid * Cx + 0];
        float c1 = s_pool[tid * Cx + 1];
        float c2 = s_pool[tid * Cx + 2];
        red_add_v4(pool_rb + tid * ROW_F4, c0, c1, c2);
    }

    // ---------------- Grid barrier ----------------
    __threadfence();                       // REDs visible before arrival RMW
    if (tid == 0) {
        unsigned long long old = atomicAdd(&g_bar, 1ULL);
        unsigned long long target = (old / NBLK + 1ULL) * NBLK;
        while (*(volatile unsigned long long*)&g_bar < target) { }
    }
    __syncthreads();
    // Phase-2 pooled reads use ld.global.cg (L2 is the coherence point).

    // ---------------- Phase 2: tiny GEMM (4 rows, threads 0..767) ----------------
    const float inv = 1.0f / (float)HW;
    const int bk0 = blockIdx.x * ROWS_PER_BLOCK;

    if (tid < Ex) {
        const float w0 = Wmat[0 * Ex + tid];
        const float w1 = Wmat[1 * Ex + tid];
        const float w2 = Wmat[2 * Ex + tid];
        const float bb = bias[tid];

#pragma unroll
        for (int r = 0; r < ROWS_PER_BLOCK; r++) {
            const int bk = bk0 + r;
            float p0 = 0.f, p1 = 0.f, p2 = 0.f;
#pragma unroll
            for (int rp = 0; rp < NREP; rp++) {
                float4 q = ldcg4(&g_pool4[((size_t)rp * BK + bk) * ROW_F4]);
                p0 += q.x; p1 += q.y; p2 += q.z;
            }
            float acc = bb;
            acc = fmaf(p0 * inv, w0, acc);
            acc = fmaf(p1 * inv, w1, acc);
            acc = fmaf(p2 * inv, w2, acc);
            out[(size_t)bk * Ex + tid] = acc;
        }
    }

    // Restore the zero-invariant for all replicas of the rows this block read.
    __syncthreads();
    if (tid < ROWS_PER_BLOCK * NREP) {
        int rp  = tid / ROWS_PER_BLOCK;
        int row = bk0 + (tid % ROWS_PER_BLOCK);
        g_pool4[((size_t)rp * BK + row) * ROW_F4] = make_float4(0.f, 0.f, 0.f, 0.f);
    }
}

extern "C" void kernel_launch(void* const* d_in, const int* in_sizes, int n_in,
                              void* d_out, int out_size) {
    const float* img  = (const float*)d_in[0];
    const int*   seg  = (const int*)d_in[1];
    const float* Wmat = (const float*)d_in[2];
    const float* bias = (const float*)d_in[3];
    float* out = (float*)d_out;

    fused_kernel<<<NBLK, TA>>>(img, seg, Wmat, bias, out);
}

// round 9
// speedup vs baseline: 1.0221x; 1.0221x over previous
#include <cuda_runtime.h>
#include <cuda_bf16.h>

// Problem constants
#define Bx 4
#define Cx 3
#define Hx 224
#define Wx 224
#define Kx 196
#define Ex 768
#define HW (Hx * Wx)               // 50176
#define BK (Bx * Kx)               // 784
#define TOTPX (Bx * HW)            // 200704

#define NBLK 148                   // one block per SM: perfect balance
#define TA 1024
#define THREADS_TOT (NBLK * TA)    // 151552

#define NREP 4                     // global-pool replicas
#define ROW_F4 8                   // 128 B per (b,k) row
#define MAXROWS 6                  // ceil(784/148)

// Replicated pooled sums: g_pool4[rep][bk][ROW_F4]; element 0 = {c0,c1,c2,pad}.
// Zero at module load; phase 2 re-zeroes consumed rows each call.
__device__ float4 g_pool4[NREP * BK * ROW_F4];

// Grid barrier: monotone epoch counter (never reset; u64 cannot overflow).
__device__ unsigned long long g_bar;

__device__ __forceinline__ void red_add_v4(float4* p, float x, float y, float z) {
    asm volatile("red.global.add.v4.f32 [%0], {%1, %2, %3, %4};"
                 :: "l"(p), "f"(x), "f"(y), "f"(z), "f"(0.0f) : "memory");
}

__device__ __forceinline__ float4 ldcg4(const float4* p) {
    float4 v;
    asm volatile("ld.global.cg.v4.f32 {%0,%1,%2,%3}, [%4];"
                 : "=f"(v.x), "=f"(v.y), "=f"(v.z), "=f"(v.w) : "l"(p));
    return v;
}

__global__ void __launch_bounds__(TA, 1)
fused_kernel(const float* __restrict__ img,
             const int* __restrict__ seg,
             const float* __restrict__ Wmat,
             const float* __restrict__ bias,
             float* __restrict__ out) {
    __shared__ float s_pool[BK * Cx];   // all 784 keys x 3 channels = 9.4 KB

    const int tid = threadIdx.x;
    const int rep = blockIdx.x & (NREP - 1);

    // ---------------- Phase 1 ----------------
    for (int i = tid; i < BK * Cx; i += TA) s_pool[i] = 0.0f;
    __syncthreads();

    const int g = blockIdx.x * TA + tid;

    // Pixel 1 (all threads): shared-memory atomics
    {
        const int p  = g;                     // < 151552 < TOTPX always
        const int b  = p / HW;
        const int hw = p - b * HW;
        const int k  = seg[p];
        const float* ib = img + (size_t)(b * Cx) * HW + hw;
        float v0 = ib[0];
        float v1 = ib[HW];
        float v2 = ib[2 * HW];
        const int key = b * Kx + k;
        atomicAdd(&s_pool[key * Cx + 0], v0);
        atomicAdd(&s_pool[key * Cx + 1], v1);
        atomicAdd(&s_pool[key * Cx + 2], v2);
    }

    // Pixel 2 (first 49152 threads): direct global vector reduction
    {
        const int p = THREADS_TOT + g;
        if (p < TOTPX) {
            const int b  = p / HW;
            const int hw = p - b * HW;
            const int k  = seg[p];
            const float* ib = img + (size_t)(b * Cx) * HW + hw;
            float v0 = ib[0];
            float v1 = ib[HW];
            float v2 = ib[2 * HW];
            red_add_v4(g_pool4 + ((size_t)rep * BK + b * Kx + k) * ROW_F4,
                       v0, v1, v2);
        }
    }

    __syncthreads();

    // Flush non-zero block partials into this block's replica
    if (tid < BK) {
        float c0 = s_pool[tid * Cx + 0];
        float c1 = s_pool[tid * Cx + 1];
        float c2 = s_pool[tid * Cx + 2];
        if (c0 != 0.0f || c1 != 0.0f || c2 != 0.0f) {
            red_add_v4(g_pool4 + ((size_t)rep * BK + tid) * ROW_F4, c0, c1, c2);
        }
    }

    // Prefetch phase-2 operands before waiting (independent of barrier)
    float w0 = 0.f, w1 = 0.f, w2 = 0.f, bb = 0.f;
    if (tid < Ex) {
        w0 = Wmat[0 * Ex + tid];
        w1 = Wmat[1 * Ex + tid];
        w2 = Wmat[2 * Ex + tid];
        bb = bias[tid];
    }

    // ---------------- Grid barrier ----------------
    __threadfence();                       // REDs visible before arrival RMW
    if (tid == 0) {
        unsigned long long old = atomicAdd(&g_bar, 1ULL);
        unsigned long long target = (old / NBLK + 1ULL) * NBLK;
        while (*(volatile unsigned long long*)&g_bar < target) { }
    }
    __syncthreads();
    // Phase-2 pooled reads use ld.global.cg (L2 is the coherence point).

    // ---------------- Phase 2: tiny GEMM (5-6 rows per block) ----------------
    const float inv = 1.0f / (float)HW;
    if (tid < Ex) {
        for (int r = blockIdx.x; r < BK; r += NBLK) {
            float p0 = 0.f, p1 = 0.f, p2 = 0.f;
#pragma unroll
            for (int rp = 0; rp < NREP; rp++) {
                float4 q = ldcg4(&g_pool4[((size_t)rp * BK + r) * ROW_F4]);
                p0 += q.x; p1 += q.y; p2 += q.z;
            }
            float acc = bb;
            acc = fmaf(p0 * inv, w0, acc);
            acc = fmaf(p1 * inv, w1, acc);
            acc = fmaf(p2 * inv, w2, acc);
            out[(size_t)r * Ex + tid] = acc;
        }
    }

    // Restore the zero-invariant for all replicas of the rows this block read.
    __syncthreads();
    if (tid < MAXROWS * NREP) {
        const int j  = tid >> 2;           // 0..5
        const int rp = tid & 3;
        const int r  = blockIdx.x + NBLK * j;
        if (r < BK) {
            g_pool4[((size_t)rp * BK + r) * ROW_F4] = make_float4(0.f, 0.f, 0.f, 0.f);
        }
    }
}

extern "C" void kernel_launch(void* const* d_in, const int* in_sizes, int n_in,
                              void* d_out, int out_size) {
    const float* img  = (const float*)d_in[0];
    const int*   seg  = (const int*)d_in[1];
    const float* Wmat = (const float*)d_in[2];
    const float* bias = (const float*)d_in[3];
    float* out = (float*)d_out;

    fused_kernel<<<NBLK, TA>>>(img, seg, Wmat, bias, out);
}

// round 10
// speedup vs baseline: 1.5182x; 1.4854x over previous
#include <cuda_runtime.h>
#include <cuda_bf16.h>

// Problem constants
#define Bx 4
#define Cx 3
#define Hx 224
#define Wx 224
#define Kx 196
#define Ex 768
#define HW (Hx * Wx)               // 50176
#define KC (Kx * Cx)               // 588
#define BK (Bx * Kx)               // 784

#define BPB 49                     // blocks per batch
#define NBLK (Bx * BPB)            // 196
#define TA 256
#define PIX_PER_BLOCK (TA * 4)     // 1024; 49*1024 = HW exactly

#define ROWS_PER_BLOCK 4           // 49 blocks * 4 rows = 196 = Kx
#define COLS_PER_THREAD (Ex / TA)  // 3

#define ROW_F4 8                   // 128 B per (b,k) row (L2-slice spread)

// Pooled sums; element 0 of each row = {c0,c1,c2,pad}. Zero at module load;
// phase 2 re-zeroes consumed rows, so the zero-invariant holds every call.
__device__ float4 g_pool4[BK * ROW_F4];

// Per-batch sub-barriers: monotone epoch counters, 128 B apart (no false
// sharing of the L2 atomic slice). u64 -> never overflows.
__device__ unsigned long long g_bar[Bx * 16];

__device__ __forceinline__ void red_add_v4(float4* p, float x, float y, float z) {
    asm volatile("red.global.add.v4.f32 [%0], {%1, %2, %3, %4};"
                 :: "l"(p), "f"(x), "f"(y), "f"(z), "f"(0.0f) : "memory");
}

__device__ __forceinline__ float4 ldcg4(const float4* p) {
    float4 v;
    asm volatile("ld.global.cg.v4.f32 {%0,%1,%2,%3}, [%4];"
                 : "=f"(v.x), "=f"(v.y), "=f"(v.z), "=f"(v.w) : "l"(p));
    return v;
}

__global__ void __launch_bounds__(TA)
fused_kernel(const float* __restrict__ img,
             const int* __restrict__ seg,
             const float* __restrict__ Wmat,
             const float* __restrict__ bias,
             float* __restrict__ out) {
    __shared__ float s_pool[KC];

    const int tid = threadIdx.x;
    const int b   = blockIdx.x / BPB;
    const int blk = blockIdx.x % BPB;

    // ---------------- Phase 1: segment-sum (R4 form: cheapest measured) ----
    for (int i = tid; i < KC; i += TA) s_pool[i] = 0.0f;
    __syncthreads();

    const int p0 = blk * PIX_PER_BLOCK + tid * 4;
    const float* img_b = img + (size_t)b * Cx * HW;
    const int*   seg_b = seg + (size_t)b * HW;

    int4   s  = *(const int4*)  (seg_b + p0);
    float4 v0 = *(const float4*)(img_b + p0);
    float4 v1 = *(const float4*)(img_b + p0 + HW);
    float4 v2 = *(const float4*)(img_b + p0 + 2 * HW);

    atomicAdd(&s_pool[s.x * Cx + 0], v0.x);
    atomicAdd(&s_pool[s.x * Cx + 1], v1.x);
    atomicAdd(&s_pool[s.x * Cx + 2], v2.x);
    atomicAdd(&s_pool[s.y * Cx + 0], v0.y);
    atomicAdd(&s_pool[s.y * Cx + 1], v1.y);
    atomicAdd(&s_pool[s.y * Cx + 2], v2.y);
    atomicAdd(&s_pool[s.z * Cx + 0], v0.z);
    atomicAdd(&s_pool[s.z * Cx + 1], v1.z);
    atomicAdd(&s_pool[s.z * Cx + 2], v2.z);
    atomicAdd(&s_pool[s.w * Cx + 0], v0.w);
    atomicAdd(&s_pool[s.w * Cx + 1], v1.w);
    atomicAdd(&s_pool[s.w * Cx + 2], v2.w);

    __syncthreads();

    // Flush: one fire-and-forget vector RED per key (196 ops, was 588 ATOMG)
    if (tid < Kx) {
        float c0 = s_pool[tid * Cx + 0];
        float c1 = s_pool[tid * Cx + 1];
        float c2 = s_pool[tid * Cx + 2];
        red_add_v4(&g_pool4[(b * Kx + tid) * ROW_F4], c0, c1, c2);
    }

    // Prefetch phase-2 operands (independent of the barrier)
    float w0c[COLS_PER_THREAD], w1c[COLS_PER_THREAD], w2c[COLS_PER_THREAD];
    float bbc[COLS_PER_THREAD];
#pragma unroll
    for (int j = 0; j < COLS_PER_THREAD; j++) {
        int e = tid + j * TA;
        w0c[j] = Wmat[0 * Ex + e];
        w1c[j] = Wmat[1 * Ex + e];
        w2c[j] = Wmat[2 * Ex + e];
        bbc[j] = bias[e];
    }

    // ---------------- Per-batch sub-barrier (49 arrivals) ----------------
    __threadfence();                       // REDs globally visible first
    if (tid == 0) {
        unsigned long long* bar = &g_bar[b * 16];
        unsigned long long old = atomicAdd(bar, 1ULL);
        unsigned long long target = (old / BPB + 1ULL) * BPB;
        while (*(volatile unsigned long long*)bar < target) { }
    }
    __syncthreads();
    // Phase-2 pooled reads use ld.global.cg (L2 is the coherence point).

    // ---------------- Phase 2: 4 rows of this block's own batch ----------
    const float inv = 1.0f / (float)HW;
    const int bk0 = b * Kx + blk * ROWS_PER_BLOCK;

    // Issue all 4 row loads up front (independent -> one L2 round-trip)
    float4 q[ROWS_PER_BLOCK];
#pragma unroll
    for (int r = 0; r < ROWS_PER_BLOCK; r++) {
        q[r] = ldcg4(&g_pool4[(bk0 + r) * ROW_F4]);
    }

#pragma unroll
    for (int r = 0; r < ROWS_PER_BLOCK; r++) {
        const int bk = bk0 + r;
        float p0 = q[r].x * inv, p1 = q[r].y * inv, p2 = q[r].z * inv;
#pragma unroll
        for (int j = 0; j < COLS_PER_THREAD; j++) {
            int e = tid + j * TA;
            float acc = bbc[j];
            acc = fmaf(p0, w0c[j], acc);
            acc = fmaf(p1, w1c[j], acc);
            acc = fmaf(p2, w2c[j], acc);
            out[(size_t)bk * Ex + e] = acc;
        }
    }

    // Restore the zero-invariant for the rows this block consumed.
    __syncthreads();
    if (tid < ROWS_PER_BLOCK) {
        g_pool4[(bk0 + tid) * ROW_F4] = make_float4(0.f, 0.f, 0.f, 0.f);
    }
}

extern "C" void kernel_launch(void* const* d_in, const int* in_sizes, int n_in,
                              void* d_out, int out_size) {
    const float* img  = (const float*)d_in[0];
    const int*   seg  = (const int*)d_in[1];
    const float* Wmat = (const float*)d_in[2];
    const float* bias = (const float*)d_in[3];
    float* out = (float*)d_out;

    fused_kernel<<<NBLK, TA>>>(img, seg, Wmat, bias, out);
}